// round 4
// baseline (speedup 1.0000x reference)
#include <cuda_runtime.h>
#include <cuda_bf16.h>
#include <cstdint>

#define N_ 128
#define C_ 81
#define A_ 8732
#define A4_ 2183          // A_/4 exactly

__device__ float    g_row[N_];
__device__ unsigned g_count;      // zero at load; last block resets -> replay-safe

// ---------------------------------------------------------------------------
// One CTA per batch row: stream plabel -> con in smem, fused masked smooth-L1,
// radix-select top-k negatives, row loss; last CTA reduces the mean.
// grid = N_, block = 1024
// ---------------------------------------------------------------------------
__global__ __launch_bounds__(1024) void k_fused(const float* __restrict__ ploc,
                                                const float* __restrict__ plabel,
                                                const float* __restrict__ gloc,
                                                const int*   __restrict__ glabel,
                                                const int*   __restrict__ domain_label,
                                                const float* __restrict__ dboxes,
                                                float* __restrict__ out)
{
    __shared__ __align__(16) unsigned s_con[A_];   // 34928 B
    __shared__ unsigned s_hist[2048];              // 8 replicated 256-bin histograms
    __shared__ unsigned s_hsum[256];
    __shared__ unsigned s_state[4];                // prefix, mask, kk, gt
    __shared__ float    s_redf[32];
    __shared__ float    s_redg[32];
    __shared__ int      s_redi[32];
    __shared__ unsigned s_last;

    const int n   = blockIdx.x;
    const int tid = threadIdx.x;

    const float4* Pb = (const float4*)(plabel + (size_t)n * C_ * A_);
    const int4*   G  = (const int4*)(glabel + (size_t)n * A_);
    const float4* PL = (const float4*)(ploc + (size_t)n * 4 * A_);
    const float4* GL = (const float4*)(gloc + (size_t)n * 4 * A_);
    const float4* DB = (const float4*)dboxes;

    float conp = 0.f, sl1 = 0.f;
    int   pc = 0;

    // ---- 3 chunks of 1024 float4-groups cover A4_ = 2183 ----
#pragma unroll
    for (int chunk = 0; chunk < 3; chunk++) {
        int grp = chunk * 1024 + tid;
        if (grp < A4_) {
            int4 g = G[grp];
            const float4* P = Pb + grp;
            float4 s  = make_float4(0.f, 0.f, 0.f, 0.f);
            float4 xg = make_float4(0.f, 0.f, 0.f, 0.f);
#pragma unroll 3
            for (int c = 0; c < C_; c++) {
                float4 x = __ldcs(P);
                P += A4_;
                if (c == g.x) xg.x = x.x;
                if (c == g.y) xg.y = x.y;
                if (c == g.z) xg.z = x.z;
                if (c == g.w) xg.w = x.w;
                s.x += __expf(x.x); s.y += __expf(x.y);
                s.z += __expf(x.z); s.w += __expf(x.w);
            }
            float lp0 = xg.x - __logf(s.x), lp1 = xg.y - __logf(s.y);
            float lp2 = xg.z - __logf(s.z), lp3 = xg.w - __logf(s.w);
            float o0 = 1.f - __expf(lp0), o1 = 1.f - __expf(lp1);
            float o2 = 1.f - __expf(lp2), o3 = 1.f - __expf(lp3);
            float c0 = -0.25f * o0 * o0 * lp0;
            float c1 = -0.25f * o1 * o1 * lp1;
            float c2 = -0.25f * o2 * o2 * lp2;
            float c3 = -0.25f * o3 * o3 * lp3;

            bool m0 = g.x > 0, m1 = g.y > 0, m2 = g.z > 0, m3 = g.w > 0;

            uint4 cw;
            cw.x = m0 ? 0u : __float_as_uint(c0);
            cw.y = m1 ? 0u : __float_as_uint(c1);
            cw.z = m2 ? 0u : __float_as_uint(c2);
            cw.w = m3 ? 0u : __float_as_uint(c3);
            ((uint4*)s_con)[grp] = cw;

            if (m0) { conp += c0; pc++; }
            if (m1) { conp += c1; pc++; }
            if (m2) { conp += c2; pc++; }
            if (m3) { conp += c3; pc++; }

            // masked smooth-L1: load loc data only if a positive in this group
            if (m0 | m1 | m2 | m3) {
                float4 plx = PL[0 * A4_ + grp], ply = PL[1 * A4_ + grp];
                float4 plw = PL[2 * A4_ + grp], plh = PL[3 * A4_ + grp];
                float4 glx = GL[0 * A4_ + grp], gly = GL[1 * A4_ + grp];
                float4 glw = GL[2 * A4_ + grp], glh = GL[3 * A4_ + grp];
                float4 dbx = DB[0 * A4_ + grp], dby = DB[1 * A4_ + grp];
                float4 dbw = DB[2 * A4_ + grp], dbh = DB[3 * A4_ + grp];

#define SL1_LANE(M, PX, PY, PW, PH, GX, GY, GW, GH, DX, DY, DW, DH)           \
                if (M) {                                                      \
                    float v0 = 10.f * (GX - DX) / DW;                         \
                    float v1 = 10.f * (GY - DY) / DH;                         \
                    float v2 = 5.f * __logf(GW / DW);                         \
                    float v3 = 5.f * __logf(GH / DH);                         \
                    float d0 = PX - v0, d1 = PY - v1;                         \
                    float d2 = PW - v2, d3 = PH - v3;                         \
                    float ad;                                                 \
                    ad = fabsf(d0); sl1 += (ad < 1.f) ? 0.5f*d0*d0 : ad-0.5f; \
                    ad = fabsf(d1); sl1 += (ad < 1.f) ? 0.5f*d1*d1 : ad-0.5f; \
                    ad = fabsf(d2); sl1 += (ad < 1.f) ? 0.5f*d2*d2 : ad-0.5f; \
                    ad = fabsf(d3); sl1 += (ad < 1.f) ? 0.5f*d3*d3 : ad-0.5f; \
                }
                SL1_LANE(m0, plx.x, ply.x, plw.x, plh.x, glx.x, gly.x, glw.x, glh.x, dbx.x, dby.x, dbw.x, dbh.x)
                SL1_LANE(m1, plx.y, ply.y, plw.y, plh.y, glx.y, gly.y, glw.y, glh.y, dbx.y, dby.y, dbw.y, dbh.y)
                SL1_LANE(m2, plx.z, ply.z, plw.z, plh.z, glx.z, gly.z, glw.z, glh.z, dbx.z, dby.z, dbw.z, dbh.z)
                SL1_LANE(m3, plx.w, ply.w, plw.w, plh.w, glx.w, gly.w, glw.w, glh.w, dbx.w, dby.w, dbw.w, dbh.w)
#undef SL1_LANE
            }
        }
    }

    // ---- block reduce conp+sl1 and pos count ----
    float tot = conp + sl1;
    for (int o = 16; o > 0; o >>= 1) {
        tot += __shfl_down_sync(0xffffffffu, tot, o);
        pc  += __shfl_down_sync(0xffffffffu, pc, o);
    }
    int wid = tid >> 5, lane = tid & 31;
    if (lane == 0) { s_redf[wid] = tot; s_redi[wid] = pc; }
    __syncthreads();
    if (tid < 32) {
        float v = s_redf[tid];
        int   p = s_redi[tid];
        for (int o = 16; o > 0; o >>= 1) {
            v += __shfl_down_sync(0xffffffffu, v, o);
            p += __shfl_down_sync(0xffffffffu, p, o);
        }
        if (tid == 0) {
            s_redf[0] = v; s_redi[0] = p;
            s_state[0] = 0u; s_state[1] = 0u; s_state[3] = 0u;
        }
    }
    __syncthreads();

    int   pos = s_redi[0];
    float ps  = s_redf[0];
    int   dl  = domain_label[n];

    if (pos == 0 || dl != 0) {
        // row contributes 0 (no positives, or src_mask = 0): skip the select
        if (tid == 0) g_row[n] = 0.f;
    } else {
        int k = 3 * pos; if (k > A_) k = A_;
        if (tid == 0) s_state[2] = (unsigned)k;
        unsigned hb = ((unsigned)(tid >> 5) & 7u) << 8;

        // 4-pass radix select for the k-th largest (con >= 0 -> uint monotone)
#pragma unroll
        for (int shift = 24; shift >= 0; shift -= 8) {
            s_hist[tid] = 0u; s_hist[tid + 1024] = 0u;
            __syncthreads();
            unsigned pref = s_state[0], msk = s_state[1];
            for (int i = tid; i < A_; i += 1024) {
                unsigned x = s_con[i];
                if ((x & msk) == pref)
                    atomicAdd(&s_hist[hb + ((x >> shift) & 255u)], 1u);
            }
            __syncthreads();
            if (tid < 256) {
                unsigned h = s_hist[tid];
#pragma unroll
                for (int j = 1; j < 8; j++) h += s_hist[j * 256 + tid];
                s_hsum[tid] = h;
            }
            __syncthreads();
            if (tid < 32) {
                unsigned base = (unsigned)tid << 3;
                unsigned lh[8], ls[8];
#pragma unroll
                for (int j = 0; j < 8; j++) lh[j] = s_hsum[base + j];
                unsigned run = 0;
#pragma unroll
                for (int j = 7; j >= 0; j--) { run += lh[j]; ls[j] = run; }
                unsigned incl = run;
#pragma unroll
                for (int o = 1; o < 32; o <<= 1) {
                    unsigned v = __shfl_down_sync(0xffffffffu, incl, o);
                    if (tid + o < 32) incl += v;
                }
                unsigned exh = incl - run;
                unsigned kk = s_state[2];
#pragma unroll
                for (int j = 0; j < 8; j++) {
                    unsigned suf = exh + ls[j];
                    unsigned gtc = suf - lh[j];
                    if (gtc < kk && suf >= kk) {
                        s_state[0] |= (base + j) << shift;
                        s_state[1] |= 0xFFu << shift;
                        s_state[2] = kk - gtc;
                        s_state[3] += gtc;
                    }
                }
            }
            __syncthreads();
        }

        unsigned T    = s_state[0];
        unsigned ties = s_state[2];   // k - count(> T)

        float sgt = 0.f;
        for (int i = tid; i < A_; i += 1024) {
            unsigned x = s_con[i];
            if (x > T) sgt += __uint_as_float(x);
        }
        for (int o = 16; o > 0; o >>= 1) sgt += __shfl_down_sync(0xffffffffu, sgt, o);
        if (lane == 0) s_redg[wid] = sgt;
        __syncthreads();
        if (tid < 32) {
            float v = s_redg[tid];
            for (int o = 16; o > 0; o >>= 1) v += __shfl_down_sync(0xffffffffu, v, o);
            if (tid == 0) {
                float topk = v + (float)ties * __uint_as_float(T);
                g_row[n] = (ps + topk) / (float)pos;
            }
        }
    }
    __syncthreads();

    // ---- last-arriving CTA computes the mean ----
    if (tid == 0) {
        __threadfence();
        unsigned old = atomicAdd(&g_count, 1u);
        s_last = (old == N_ - 1u) ? 1u : 0u;
    }
    __syncthreads();
    if (s_last) {
        __threadfence();
        float v = (tid < N_) ? g_row[tid] : 0.f;
        for (int o = 16; o > 0; o >>= 1) v += __shfl_down_sync(0xffffffffu, v, o);
        if (lane == 0) s_redg[wid] = v;
        __syncthreads();
        if (tid < 32) {
            float t = (tid < 4) ? s_redg[tid] : 0.f;   // only warps 0-3 held rows
            for (int o = 2; o > 0; o >>= 1) t += __shfl_down_sync(0xffffffffu, t, o);
            if (tid == 0) {
                out[0] = t / (float)N_;
                g_count = 0u;   // reset for next graph replay
            }
        }
    }
}

extern "C" void kernel_launch(void* const* d_in, const int* in_sizes, int n_in,
                              void* d_out, int out_size)
{
    const float* ploc         = (const float*)d_in[0];
    const float* plabel       = (const float*)d_in[1];
    const float* gloc         = (const float*)d_in[2];
    const int*   glabel       = (const int*)  d_in[3];
    const int*   domain_label = (const int*)  d_in[4];
    const float* dboxes       = (const float*)d_in[5];
    float* out = (float*)d_out;

    k_fused<<<N_, 1024>>>(ploc, plabel, gloc, glabel, domain_label, dboxes, out);
}

// round 5
// speedup vs baseline: 1.5052x; 1.5052x over previous
#include <cuda_runtime.h>
#include <cuda_bf16.h>
#include <cstdint>

#define N_ 128
#define C_ 81
#define A_ 8732
#define A4_ 2183          // A_/4 exactly

// Scratch (device globals — no allocations allowed)
__device__ unsigned g_con[N_ * A_];        // focal bits (written only for dl==0 rows)
__device__ float    g_partcon[N_ * 16];    // per (row, blk): sum mask*con
__device__ int      g_partpos[N_ * 16];    // per (row, blk): positive count
__device__ float    g_row[N_];
__device__ unsigned g_count;               // zero at load; last CTA resets -> replay-safe

// ---------------------------------------------------------------------------
// Kernel A: focal loss per anchor. Entire block early-exits when the row's
// domain_label != 0 (source_mask zeroes the whole row) -> ~half the traffic.
// grid = (9, N), block = 256, lean registers for occupancy.
// ---------------------------------------------------------------------------
__global__ __launch_bounds__(256, 8) void kA_focal(const float* __restrict__ plabel,
                                                   const int*   __restrict__ glabel,
                                                   const int*   __restrict__ domain_label)
{
    const int n = blockIdx.y;
    if (domain_label[n] != 0) return;          // row contributes exactly 0

    int idx = blockIdx.x * 256 + threadIdx.x;
    bool valid = (idx < A4_);
    int ii = valid ? idx : (A4_ - 1);

    const float4* P = (const float4*)(plabel + (size_t)n * C_ * A_) + ii;
    int4 g = ((const int4*)(glabel + (size_t)n * A_))[ii];

    float4 s  = make_float4(0.f, 0.f, 0.f, 0.f);
    float4 xg = make_float4(0.f, 0.f, 0.f, 0.f);
#pragma unroll 3
    for (int c = 0; c < C_; c++) {
        float4 x = __ldcs(P);
        P += A4_;
        if (c == g.x) xg.x = x.x;
        if (c == g.y) xg.y = x.y;
        if (c == g.z) xg.z = x.z;
        if (c == g.w) xg.w = x.w;
        s.x += __expf(x.x); s.y += __expf(x.y);
        s.z += __expf(x.z); s.w += __expf(x.w);
    }

    float lp0 = xg.x - __logf(s.x), lp1 = xg.y - __logf(s.y);
    float lp2 = xg.z - __logf(s.z), lp3 = xg.w - __logf(s.w);
    float o0 = 1.f - __expf(lp0), o1 = 1.f - __expf(lp1);
    float o2 = 1.f - __expf(lp2), o3 = 1.f - __expf(lp3);
    float c0 = -0.25f * o0 * o0 * lp0;
    float c1 = -0.25f * o1 * o1 * lp1;
    float c2 = -0.25f * o2 * o2 * lp2;
    float c3 = -0.25f * o3 * o3 * lp3;

    bool m0 = g.x > 0, m1 = g.y > 0, m2 = g.z > 0, m3 = g.w > 0;

    uint4 cw;
    cw.x = m0 ? 0u : __float_as_uint(c0);
    cw.y = m1 ? 0u : __float_as_uint(c1);
    cw.z = m2 ? 0u : __float_as_uint(c2);
    cw.w = m3 ? 0u : __float_as_uint(c3);
    ((uint4*)g_con)[(size_t)n * A4_ + ii] = cw;

    float contrib = 0.f;
    int pc = 0;
    if (valid) {
        if (m0) { contrib += c0; pc++; }
        if (m1) { contrib += c1; pc++; }
        if (m2) { contrib += c2; pc++; }
        if (m3) { contrib += c3; pc++; }
    }
    for (int o = 16; o > 0; o >>= 1) {
        contrib += __shfl_down_sync(0xffffffffu, contrib, o);
        pc      += __shfl_down_sync(0xffffffffu, pc, o);
    }
    __shared__ float sw[8];
    __shared__ int   swp[8];
    int wid = threadIdx.x >> 5, lane = threadIdx.x & 31;
    if (lane == 0) { sw[wid] = contrib; swp[wid] = pc; }
    __syncthreads();
    if (threadIdx.x == 0) {
        float t = 0.f; int tp = 0;
#pragma unroll
        for (int j = 0; j < 8; j++) { t += sw[j]; tp += swp[j]; }
        g_partcon[n * 16 + blockIdx.x] = t;
        g_partpos[n * 16 + blockIdx.x] = tp;
    }
}

// ---------------------------------------------------------------------------
// Kernel T (tail): per-row loc pass + radix-select top-k + row loss + mean.
// grid = N_, block = 1024. Rows with dl!=0 or pos==0 short-circuit to 0.
// Last-arriving CTA reduces the 128-row mean (atomic counter, self-resetting).
// ---------------------------------------------------------------------------
__global__ __launch_bounds__(1024) void kT_tail(const float* __restrict__ ploc,
                                                const float* __restrict__ gloc,
                                                const int*   __restrict__ glabel,
                                                const int*   __restrict__ domain_label,
                                                const float* __restrict__ dboxes,
                                                float* __restrict__ out)
{
    __shared__ __align__(16) unsigned s_con[A_];
    __shared__ unsigned s_hist[2048];
    __shared__ unsigned s_hsum[256];
    __shared__ unsigned s_state[4];      // prefix, mask, kk, gt
    __shared__ float    s_redf[32];
    __shared__ int      s_pn;
    __shared__ float    s_pc;
    __shared__ unsigned s_last;

    const int n   = blockIdx.x;
    const int tid = threadIdx.x;
    const int wid = tid >> 5, lane = tid & 31;
    const int dl  = domain_label[n];

    if (dl == 0) {
        if (tid == 0) {
            float ps = 0.f; int pp = 0;
#pragma unroll
            for (int j = 0; j < 9; j++) { ps += g_partcon[n * 16 + j]; pp += g_partpos[n * 16 + j]; }
            s_pc = ps; s_pn = pp;
            s_state[0] = 0u; s_state[1] = 0u; s_state[3] = 0u;
        }
        __syncthreads();
        int pos = s_pn;

        if (pos > 0) {
            // ---- load con row into smem + masked smooth-L1 in one sweep ----
            const uint4*  gc = (const uint4*)g_con + (size_t)n * A4_;
            const int4*   G  = (const int4*)(glabel + (size_t)n * A_);
            const float4* PL = (const float4*)(ploc + (size_t)n * 4 * A_);
            const float4* GL = (const float4*)(gloc + (size_t)n * 4 * A_);
            const float4* DB = (const float4*)dboxes;

            float sl1 = 0.f;
#pragma unroll
            for (int chunk = 0; chunk < 3; chunk++) {
                int grp = chunk * 1024 + tid;
                if (grp < A4_) {
                    ((uint4*)s_con)[grp] = gc[grp];
                    int4 g = G[grp];
                    bool m0 = g.x > 0, m1 = g.y > 0, m2 = g.z > 0, m3 = g.w > 0;
                    if (m0 | m1 | m2 | m3) {
                        float4 plx = PL[0 * A4_ + grp], ply = PL[1 * A4_ + grp];
                        float4 plw = PL[2 * A4_ + grp], plh = PL[3 * A4_ + grp];
                        float4 glx = GL[0 * A4_ + grp], gly = GL[1 * A4_ + grp];
                        float4 glw = GL[2 * A4_ + grp], glh = GL[3 * A4_ + grp];
                        float4 dbx = DB[0 * A4_ + grp], dby = DB[1 * A4_ + grp];
                        float4 dbw = DB[2 * A4_ + grp], dbh = DB[3 * A4_ + grp];
#define SL1_LANE(M, PX, PY, PW, PH, GX, GY, GW, GH, DX, DY, DW, DH)           \
                        if (M) {                                              \
                            float v0 = 10.f * (GX - DX) / DW;                 \
                            float v1 = 10.f * (GY - DY) / DH;                 \
                            float v2 = 5.f * __logf(GW / DW);                 \
                            float v3 = 5.f * __logf(GH / DH);                 \
                            float d0 = PX - v0, d1 = PY - v1;                 \
                            float d2 = PW - v2, d3 = PH - v3;                 \
                            float ad;                                         \
                            ad = fabsf(d0); sl1 += (ad < 1.f) ? 0.5f*d0*d0 : ad-0.5f; \
                            ad = fabsf(d1); sl1 += (ad < 1.f) ? 0.5f*d1*d1 : ad-0.5f; \
                            ad = fabsf(d2); sl1 += (ad < 1.f) ? 0.5f*d2*d2 : ad-0.5f; \
                            ad = fabsf(d3); sl1 += (ad < 1.f) ? 0.5f*d3*d3 : ad-0.5f; \
                        }
                        SL1_LANE(m0, plx.x, ply.x, plw.x, plh.x, glx.x, gly.x, glw.x, glh.x, dbx.x, dby.x, dbw.x, dbh.x)
                        SL1_LANE(m1, plx.y, ply.y, plw.y, plh.y, glx.y, gly.y, glw.y, glh.y, dbx.y, dby.y, dbw.y, dbh.y)
                        SL1_LANE(m2, plx.z, ply.z, plw.z, plh.z, glx.z, gly.z, glw.z, glh.z, dbx.z, dby.z, dbw.z, dbh.z)
                        SL1_LANE(m3, plx.w, ply.w, plw.w, plh.w, glx.w, gly.w, glw.w, glh.w, dbx.w, dby.w, dbw.w, dbh.w)
#undef SL1_LANE
                    }
                }
            }

            // reduce sl1
            for (int o = 16; o > 0; o >>= 1) sl1 += __shfl_down_sync(0xffffffffu, sl1, o);
            if (lane == 0) s_redf[wid] = sl1;

            int k = 3 * pos; if (k > A_) k = A_;
            if (tid == 0) s_state[2] = (unsigned)k;
            __syncthreads();

            float sl1_sum;
            {
                float v = (tid < 32) ? s_redf[tid] : 0.f;
                if (tid < 32)
                    for (int o = 16; o > 0; o >>= 1) v += __shfl_down_sync(0xffffffffu, v, o);
                if (tid == 0) s_redf[0] = v;
            }
            __syncthreads();
            sl1_sum = s_redf[0];

            // ---- 4-pass radix select for k-th largest ----
            unsigned hb = ((unsigned)(tid >> 5) & 7u) << 8;
#pragma unroll
            for (int shift = 24; shift >= 0; shift -= 8) {
                s_hist[tid] = 0u; s_hist[tid + 1024] = 0u;
                __syncthreads();
                unsigned pref = s_state[0], msk = s_state[1];
                for (int i = tid; i < A_; i += 1024) {
                    unsigned x = s_con[i];
                    if ((x & msk) == pref)
                        atomicAdd(&s_hist[hb + ((x >> shift) & 255u)], 1u);
                }
                __syncthreads();
                if (tid < 256) {
                    unsigned h = s_hist[tid];
#pragma unroll
                    for (int j = 1; j < 8; j++) h += s_hist[j * 256 + tid];
                    s_hsum[tid] = h;
                }
                __syncthreads();
                if (tid < 32) {
                    unsigned base = (unsigned)tid << 3;
                    unsigned lh[8], ls[8];
#pragma unroll
                    for (int j = 0; j < 8; j++) lh[j] = s_hsum[base + j];
                    unsigned run = 0;
#pragma unroll
                    for (int j = 7; j >= 0; j--) { run += lh[j]; ls[j] = run; }
                    unsigned incl = run;
#pragma unroll
                    for (int o = 1; o < 32; o <<= 1) {
                        unsigned v = __shfl_down_sync(0xffffffffu, incl, o);
                        if (tid + o < 32) incl += v;
                    }
                    unsigned exh = incl - run;
                    unsigned kk = s_state[2];
#pragma unroll
                    for (int j = 0; j < 8; j++) {
                        unsigned suf = exh + ls[j];
                        unsigned gtc = suf - lh[j];
                        if (gtc < kk && suf >= kk) {
                            s_state[0] |= (base + j) << shift;
                            s_state[1] |= 0xFFu << shift;
                            s_state[2] = kk - gtc;
                            s_state[3] += gtc;
                        }
                    }
                }
                __syncthreads();
            }

            unsigned T    = s_state[0];
            unsigned ties = s_state[2];   // k - count(> T)

            float sgt = 0.f;
            for (int i = tid; i < A_; i += 1024) {
                unsigned x = s_con[i];
                if (x > T) sgt += __uint_as_float(x);
            }
            for (int o = 16; o > 0; o >>= 1) sgt += __shfl_down_sync(0xffffffffu, sgt, o);
            if (lane == 0) s_redf[wid] = sgt;
            __syncthreads();
            if (tid < 32) {
                float v = s_redf[tid];
                for (int o = 16; o > 0; o >>= 1) v += __shfl_down_sync(0xffffffffu, v, o);
                if (tid == 0) {
                    float topk = v + (float)ties * __uint_as_float(T);
                    g_row[n] = (s_pc + sl1_sum + topk) / (float)pos;
                }
            }
        } else {
            if (tid == 0) g_row[n] = 0.f;
        }
    } else {
        if (tid == 0) g_row[n] = 0.f;
    }
    __syncthreads();

    // ---- last-arriving CTA computes the mean ----
    if (tid == 0) {
        __threadfence();
        unsigned old = atomicAdd(&g_count, 1u);
        s_last = (old == N_ - 1u) ? 1u : 0u;
    }
    __syncthreads();
    if (s_last) {
        __threadfence();
        float v = (tid < N_) ? g_row[tid] : 0.f;
        for (int o = 16; o > 0; o >>= 1) v += __shfl_down_sync(0xffffffffu, v, o);
        if (lane == 0) s_redf[wid] = v;
        __syncthreads();
        if (tid < 32) {
            float t = (tid < 4) ? s_redf[tid] : 0.f;   // warps 0-3 held the 128 rows
            for (int o = 2; o > 0; o >>= 1) t += __shfl_down_sync(0xffffffffu, t, o);
            if (tid == 0) {
                out[0] = t / (float)N_;
                g_count = 0u;   // reset for next graph replay
            }
        }
    }
}

extern "C" void kernel_launch(void* const* d_in, const int* in_sizes, int n_in,
                              void* d_out, int out_size)
{
    const float* ploc         = (const float*)d_in[0];
    const float* plabel       = (const float*)d_in[1];
    const float* gloc         = (const float*)d_in[2];
    const int*   glabel       = (const int*)  d_in[3];
    const int*   domain_label = (const int*)  d_in[4];
    const float* dboxes       = (const float*)d_in[5];
    float* out = (float*)d_out;

    dim3 g1(9, N_);
    kA_focal<<<g1, 256>>>(plabel, glabel, domain_label);
    kT_tail<<<N_, 1024>>>(ploc, gloc, glabel, domain_label, dboxes, out);
}